// round 1
// baseline (speedup 1.0000x reference)
#include <cuda_runtime.h>

// Geometry constants (fixed by the problem)
#define NCHANS   2560
#define T        256
#define CT       (NCHANS * T)        // 655360
#define NCELLS   40000
#define NCONTRIB (2 * NCELLS * 3)    // 240000 (face, cell, plane) contributions
#define BATCH    256                  // contributors staged per __syncthreads round

// ---------------- device scratch (static: no allocations allowed) ------------
__device__ int   g_count[NCHANS];
__device__ int   g_cursor[NCHANS];
__device__ int   g_offsets[NCHANS + 1];
__device__ int   g_cellchan[NCONTRIB];  // channel of contribution e = (f*NCELLS+cell)*3+p
__device__ int   g_entries[NCONTRIB];   // CSR payload: the contribution id e
__device__ float g_M[6];                // collapsed W1@W2, layout M[p*2+o]
__device__ float g_c[2];                // collapsed b1@W2 + b2

// ---------------- kernel 1: prep — collapse MLP, zero counters ---------------
__global__ void prep_kernel(const float* __restrict__ W1, const float* __restrict__ b1,
                            const float* __restrict__ W2, const float* __restrict__ b2) {
    int tid = blockIdx.x * blockDim.x + threadIdx.x;
    if (tid < NCHANS) { g_count[tid] = 0; g_cursor[tid] = 0; }
    if (blockIdx.x == 0) {
        if (threadIdx.x < 6) {
            int p = threadIdx.x >> 1, o = threadIdx.x & 1;
            float s = 0.f;
            #pragma unroll
            for (int h = 0; h < 8; h++) s = fmaf(W1[p * 8 + h], W2[h * 2 + o], s);
            g_M[threadIdx.x] = s;               // index == p*2+o
        } else if (threadIdx.x < 8) {
            int o = threadIdx.x - 6;
            float s = b2[o];
            #pragma unroll
            for (int h = 0; h < 8; h++) s = fmaf(b1[h], W2[h * 2 + o], s);
            g_c[o] = s;
        }
    }
}

// ---------------- kernel 2: relu(x) -> out feature 0 (vectorized) ------------
__global__ void relu_kernel(const float4* __restrict__ x, float4* __restrict__ out) {
    int i = blockIdx.x * blockDim.x + threadIdx.x;
    if (i < CT / 4) {
        float4 v = x[i];
        v.x = fmaxf(v.x, 0.f); v.y = fmaxf(v.y, 0.f);
        v.z = fmaxf(v.z, 0.f); v.w = fmaxf(v.w, 0.f);
        out[i] = v;
    }
}

// ---------------- kernel 3: resolve channels + count per channel -------------
__global__ void count_kernel(const int* __restrict__ gi0, const int* __restrict__ gi1,
                             const int* __restrict__ wc00, const int* __restrict__ wc01,
                             const int* __restrict__ wc02, const int* __restrict__ wc10,
                             const int* __restrict__ wc11, const int* __restrict__ wc12) {
    int e = blockIdx.x * blockDim.x + threadIdx.x;
    if (e >= NCONTRIB) return;
    int f = e / (NCELLS * 3);
    int r = e - f * (NCELLS * 3);         // cell*3 + p within face
    int p = r % 3;
    const int* gi = f ? gi1 : gi0;
    int w = gi[r];                        // wire index for (cell, p)
    const int* wc;
    if (f == 0) wc = (p == 0) ? wc00 : (p == 1) ? wc01 : wc02;
    else        wc = (p == 0) ? wc10 : (p == 1) ? wc11 : wc12;
    int ch = wc[2 * w + 1];               // wc rows are (wire_ident=arange, channel)
    g_cellchan[e] = ch;
    atomicAdd(&g_count[ch], 1);
}

// ---------------- kernel 4: exclusive scan over 2560 counts ------------------
__global__ void scan_kernel() {
    __shared__ int part[1024];
    int th = threadIdx.x;
    int base = th * 4;                    // 640 threads cover 2560
    int local[4];
    int s = 0;
    #pragma unroll
    for (int i = 0; i < 4; i++) {
        int idx = base + i;
        int v = (idx < NCHANS) ? g_count[idx] : 0;
        local[i] = s; s += v;
    }
    part[th] = s;
    __syncthreads();
    // Hillis-Steele inclusive scan over 1024 partials
    for (int off = 1; off < 1024; off <<= 1) {
        int v = part[th];
        int add = (th >= off) ? part[th - off] : 0;
        __syncthreads();
        part[th] = v + add;
        __syncthreads();
    }
    int chunk_excl = (th == 0) ? 0 : part[th - 1];
    #pragma unroll
    for (int i = 0; i < 4; i++) {
        int idx = base + i;
        if (idx < NCHANS) g_offsets[idx] = chunk_excl + local[i];
    }
    if (th == 639) g_offsets[NCHANS] = part[639];
}

// ---------------- kernel 5: CSR fill -----------------------------------------
__global__ void fill_kernel() {
    int e = blockIdx.x * blockDim.x + threadIdx.x;
    if (e >= NCONTRIB) return;
    int ch = g_cellchan[e];
    int pos = atomicAdd(&g_cursor[ch], 1);
    g_entries[g_offsets[ch] + pos] = e;
}

// ---------------- kernel 6: per-channel gather + max (no atomics) ------------
// One block per channel; thread t handles tick t. Reads relu(x) from out
// feature 0 (written by relu_kernel), writes out features 1 and 2.
__global__ void __launch_bounds__(T) gather_kernel(float* __restrict__ out) {
    const int c = blockIdx.x;
    const int t = threadIdx.x;
    const float* __restrict__ xr = out;           // relu(x) lives at out[0 .. CT)
    const float xown = xr[c * T + t];

    const float M00 = g_M[0], M01 = g_M[1];
    const float M10 = g_M[2], M11 = g_M[3];
    const float M20 = g_M[4], M21 = g_M[5];
    const float c0 = g_c[0], c1 = g_c[1];

    const int beg = g_offsets[c], end = g_offsets[c + 1];
    float m0 = 0.f, m1 = 0.f;                      // zeros-init => clamp at 0 for free

    __shared__ int4 sch[BATCH];                    // (ch0, ch1, ch2, pown)

    for (int kb = beg; kb < end; kb += BATCH) {
        int nb = min(BATCH, end - kb);
        if (t < nb) {
            int e = g_entries[kb + t];
            int cellbase = (e / 3) * 3;
            int pown = e - cellbase;
            sch[t] = make_int4(g_cellchan[cellbase + 0],
                               g_cellchan[cellbase + 1],
                               g_cellchan[cellbase + 2], pown);
        }
        __syncthreads();
        #pragma unroll 4
        for (int i = 0; i < nb; i++) {
            int4 s = sch[i];
            // own-plane row is register-resident; predicated loads skip it
            float a0 = (s.w == 0) ? xown : __ldg(&xr[s.x * T + t]);
            float a1 = (s.w == 1) ? xown : __ldg(&xr[s.y * T + t]);
            float a2 = (s.w == 2) ? xown : __ldg(&xr[s.z * T + t]);
            float y0 = fmaf(a0, M00, fmaf(a1, M10, fmaf(a2, M20, c0)));
            float y1 = fmaf(a0, M01, fmaf(a1, M11, fmaf(a2, M21, c1)));
            m0 = fmaxf(m0, y0);
            m1 = fmaxf(m1, y1);
        }
        __syncthreads();
    }
    out[CT + c * T + t]     = m0;
    out[2 * CT + c * T + t] = m1;
}

// ---------------- launch ------------------------------------------------------
extern "C" void kernel_launch(void* const* d_in, const int* in_sizes, int n_in,
                              void* d_out, int out_size) {
    const float* x   = (const float*)d_in[0];
    const float* W1  = (const float*)d_in[1];
    const float* b1  = (const float*)d_in[2];
    const float* W2  = (const float*)d_in[3];
    const float* b2  = (const float*)d_in[4];
    const int* gi0   = (const int*)d_in[5];
    const int* gi1   = (const int*)d_in[6];
    const int* wc00  = (const int*)d_in[7];
    const int* wc01  = (const int*)d_in[8];
    const int* wc02  = (const int*)d_in[9];
    const int* wc10  = (const int*)d_in[10];
    const int* wc11  = (const int*)d_in[11];
    const int* wc12  = (const int*)d_in[12];
    float* out = (float*)d_out;

    prep_kernel<<<10, 256>>>(W1, b1, W2, b2);
    relu_kernel<<<(CT / 4 + 255) / 256, 256>>>((const float4*)x, (float4*)out);
    count_kernel<<<(NCONTRIB + 255) / 256, 256>>>(gi0, gi1, wc00, wc01, wc02,
                                                  wc10, wc11, wc12);
    scan_kernel<<<1, 1024>>>();
    fill_kernel<<<(NCONTRIB + 255) / 256, 256>>>();
    gather_kernel<<<NCHANS, T>>>(out);
}